// round 1
// baseline (speedup 1.0000x reference)
#include <cuda_runtime.h>
#include <cstdint>
#include <float.h>
#include <math.h>

// Problem constants (fixed by the dataset)
#define TT 64
#define UU 142
#define II 4500
#define BB 16384
#define KK 10

#define NPER 5            // ceil(142/32) entries per lane
#define FULL_MASK 0xFFFFFFFFu

__global__ __launch_bounds__(256)
void ucf_kernel(const float* __restrict__ qos,      // (T,U,I)
                const float* __restrict__ uavg,     // (T,U)
                const float* __restrict__ sim,      // (U,U)
                const int*   __restrict__ user_id,  // (B,)
                const int*   __restrict__ item_id,  // (B,)
                const int*   __restrict__ time_id,  // (B,)
                float*       __restrict__ out)      // (B,)
{
    const int warp = (blockIdx.x * blockDim.x + threadIdx.x) >> 5;
    const int lane = threadIdx.x & 31;
    if (warp >= BB) return;

    const int u = user_id[warp];
    const int i = item_id[warp];
    const int t = time_id[warp];

    const float* __restrict__ qbase = qos + (size_t)t * (UU * II) + i;
    const float* __restrict__ srow  = sim + (size_t)u * UU;
    const float* __restrict__ arow  = uavg + (size_t)t * UU;

    // Each lane owns users v = lane + 32*j, j in [0,5)
    float sval[NPER];   // masked similarity (0 if unrated / invalid -> -FLT_MAX)
    float rval[NPER];   // qos rating r_vs

    #pragma unroll
    for (int j = 0; j < NPER; j++) {
        const int v = lane + 32 * j;
        float q = 0.0f;
        float s = -FLT_MAX;              // invalid sentinel (real sims >= -1)
        if (v < UU) {
            q = __ldg(qbase + (size_t)v * II);   // scattered gather (1 sector each)
            s = (q > 0.0f) ? __ldg(srow + v) : 0.0f;
        }
        sval[j] = s;
        rval[j] = q;
    }

    // Iterative warp-wide top-K argmax. Tie-break: lowest index (matches
    // jax.lax.top_k). Selected entries tracked via per-lane bitmask.
    unsigned selmask = 0;
    float Spart = 0.0f;   // per-lane partial sum of selected sims

    #pragma unroll
    for (int k = 0; k < KK; k++) {
        // local best among this lane's unselected entries
        float bv = -FLT_MAX;
        int   bi = 0x7FFFFFFF;
        #pragma unroll
        for (int j = 0; j < NPER; j++) {
            if (!((selmask >> j) & 1u)) {
                const int v = lane + 32 * j;
                const float s = sval[j];
                if (s > bv || (s == bv && v < bi)) { bv = s; bi = v; }
            }
        }
        // butterfly reduce (value desc, index asc) -> all lanes agree
        #pragma unroll
        for (int off = 16; off > 0; off >>= 1) {
            const float ov = __shfl_xor_sync(FULL_MASK, bv, off);
            const int   oi = __shfl_xor_sync(FULL_MASK, bi, off);
            if (ov > bv || (ov == bv && oi < bi)) { bv = ov; bi = oi; }
        }
        // owning lane records the selection
        if ((bi & 31) == lane) {
            selmask |= 1u << (bi >> 5);
            Spart += bv;
        }
    }

    // total selected-sim sum S across warp
    float S = Spart;
    #pragma unroll
    for (int off = 16; off > 0; off >>= 1)
        S += __shfl_xor_sync(FULL_MASK, S, off);

    const float denom = S + 1e-8f;

    // accumulate sum_k w_k * (r_k - avg_k) with per-element nan_to_num(w)
    float acc = 0.0f;
    #pragma unroll
    for (int j = 0; j < NPER; j++) {
        if ((selmask >> j) & 1u) {
            const int v = lane + 32 * j;
            float w = sval[j] / denom;
            if (isnan(w))      w = 0.0f;
            else if (isinf(w)) w = copysignf(3.4028234663852886e38f, w);
            acc += w * (rval[j] - __ldg(arow + v));
        }
    }
    #pragma unroll
    for (int off = 16; off > 0; off >>= 1)
        acc += __shfl_xor_sync(FULL_MASK, acc, off);

    if (lane == 0)
        out[warp] = __ldg(arow + u) + acc;
}

extern "C" void kernel_launch(void* const* d_in, const int* in_sizes, int n_in,
                              void* d_out, int out_size)
{
    const float* qos   = (const float*)d_in[0];  // (64,142,4500)
    const float* uavg  = (const float*)d_in[1];  // (64,142)
    const float* sim   = (const float*)d_in[2];  // (142,142)
    const int*   uid   = (const int*)  d_in[3];  // (16384,)
    const int*   iid   = (const int*)  d_in[4];  // (16384,)
    const int*   tid   = (const int*)  d_in[5];  // (16384,)
    float*       out   = (float*)d_out;          // (16384,)

    const int threads = 256;                 // 8 warps/block, 1 warp per batch row
    const int blocks  = (BB * 32) / threads; // 2048
    ucf_kernel<<<blocks, threads>>>(qos, uavg, sim, uid, iid, tid, out);
}

// round 3
// speedup vs baseline: 1.4344x; 1.4344x over previous
#include <cuda_runtime.h>
#include <cstdint>
#include <float.h>
#include <math.h>

// Problem constants (fixed by the dataset)
#define TT 64
#define UU 142
#define II 4500
#define BB 16384
#define KK 10

#define NPER 5            // lane-major: lane owns users v = 5*lane + j
#define FULL_MASK 0xFFFFFFFFu

// order-preserving float->uint map (monotone increasing); 0 reserved as
// "invalid/selected" sentinel (all real keys for sim in [-1,1] are > 0)
__device__ __forceinline__ unsigned f2ord(float f) {
    unsigned b = __float_as_uint(f);
    return (b & 0x80000000u) ? ~b : (b | 0x80000000u);
}

__global__ __launch_bounds__(256)
void ucf_kernel(const float* __restrict__ qos,      // (T,U,I)
                const float* __restrict__ uavg,     // (T,U)
                const float* __restrict__ sim,      // (U,U)
                const int*   __restrict__ user_id,  // (B,)
                const int*   __restrict__ item_id,  // (B,)
                const int*   __restrict__ time_id,  // (B,)
                float*       __restrict__ out)      // (B,)
{
    const int warp = (blockIdx.x * blockDim.x + threadIdx.x) >> 5;
    const int lane = threadIdx.x & 31;
    if (warp >= BB) return;

    const int u = user_id[warp];
    const int i = item_id[warp];
    const int t = time_id[warp];

    const float* __restrict__ qbase = qos + (size_t)t * (UU * II) + i;
    const float* __restrict__ srow  = sim + (size_t)u * UU;
    const float* __restrict__ arow  = uavg + (size_t)t * UU;

    // Lane-major ownership: v = 5*lane + j  (lanes 0..27 own 5, lane 28 owns 2)
    float    rval[NPER];   // qos rating r_vs
    float    sval[NPER];   // masked similarity (0 if unrated)
    unsigned ordu[NPER];   // orderable key; 0 = invalid/consumed

    const int vbase = lane * NPER;

    // Issue all gathers first (MLP=5 hides DRAM latency), sims unconditionally.
    float qv[NPER], sv[NPER];
    #pragma unroll
    for (int j = 0; j < NPER; j++) {
        const int v = vbase + j;
        const bool ok = (v < UU);
        qv[j] = ok ? __ldg(qbase + (size_t)v * II) : 0.0f;
        sv[j] = ok ? __ldg(srow + v) : 0.0f;
    }
    #pragma unroll
    for (int j = 0; j < NPER; j++) {
        const int v = vbase + j;
        const bool ok = (v < UU);
        const float q = qv[j];
        const float s = (ok && q > 0.0f) ? sv[j] : 0.0f;
        rval[j] = q;
        sval[j] = s;
        ordu[j] = ok ? f2ord(s) : 0u;   // invalid lanes -> sentinel 0
    }

    // Iterative top-K via redux.max + ballot. Tie-break: lowest global index
    // (lane-major => lowest lane, then lowest j; local scan uses strict '>'
    // with ascending j => lowest j).
    unsigned selmask = 0;
    float Spart = 0.0f;

    #pragma unroll
    for (int k = 0; k < KK; k++) {
        unsigned bestord = 0u;
        int bestj = 0;
        #pragma unroll
        for (int j = 0; j < NPER; j++) {
            if (ordu[j] > bestord) { bestord = ordu[j]; bestj = j; }
        }
        const unsigned maxord = __reduce_max_sync(FULL_MASK, bestord);
        const unsigned winners = __ballot_sync(FULL_MASK, bestord == maxord);
        const int winner = __ffs(winners) - 1;
        if (lane == winner) {
            #pragma unroll
            for (int j = 0; j < NPER; j++) {
                if (j == bestj) {
                    Spart += sval[j];
                    ordu[j] = 0u;
                    selmask |= 1u << j;
                }
            }
        }
    }

    // total selected-sim sum S across warp
    float S = Spart;
    #pragma unroll
    for (int off = 16; off > 0; off >>= 1)
        S += __shfl_xor_sync(FULL_MASK, S, off);

    const float denom = S + 1e-8f;

    // sum_k w_k * (r_k - avg_k), with per-element nan_to_num(w)
    float acc = 0.0f;
    #pragma unroll
    for (int j = 0; j < NPER; j++) {
        if ((selmask >> j) & 1u) {
            const int v = vbase + j;
            float w = sval[j] / denom;
            if (isnan(w))      w = 0.0f;
            else if (isinf(w)) w = copysignf(3.4028234663852886e38f, w);
            acc += w * (rval[j] - __ldg(arow + v));
        }
    }
    #pragma unroll
    for (int off = 16; off > 0; off >>= 1)
        acc += __shfl_xor_sync(FULL_MASK, acc, off);

    if (lane == 0)
        out[warp] = __ldg(arow + u) + acc;
}

extern "C" void kernel_launch(void* const* d_in, const int* in_sizes, int n_in,
                              void* d_out, int out_size)
{
    const float* qos   = (const float*)d_in[0];  // (64,142,4500)
    const float* uavg  = (const float*)d_in[1];  // (64,142)
    const float* sim   = (const float*)d_in[2];  // (142,142)
    const int*   uid   = (const int*)  d_in[3];  // (16384,)
    const int*   iid   = (const int*)  d_in[4];  // (16384,)
    const int*   tid   = (const int*)  d_in[5];  // (16384,)
    float*       out   = (float*)d_out;          // (16384,)

    const int threads = 256;                 // 8 warps/block, 1 warp per batch row
    const int blocks  = (BB * 32) / threads; // 2048
    ucf_kernel<<<blocks, threads>>>(qos, uavg, sim, uid, iid, tid, out);
}